// round 6
// baseline (speedup 1.0000x reference)
#include <cuda_runtime.h>
#include <math.h>

// Problem constants (fixed per reference)
#define BSZ   4
#define TLEN  2048
#define DMODEL 1024
#define HEADS 16
#define HDIM  64
#define RAD   4
#define MROWS (BSZ * TLEN)   // 8192

// Scratch (no cudaMalloc allowed) — __device__ globals.
__device__ float g_qkv[(size_t)MROWS * 3 * DMODEL];  // [8192, 3072]
__device__ float g_att[(size_t)MROWS * DMODEL];      // [8192, 1024]

// ---------------------------------------------------------------------------
// SGEMM (TN): C[M,N] = A[M,K] @ B[N,K]^T + bias[N]
// A row-major [M,K], B row-major [N,K] (exactly x @ w.T layout).
// Tiles: BM=BN=128, BK=8. 256 threads, 8x8 microtile per thread.
// Smem padded to 132 floats/row: transposed stores AND float4 reads are
// bank-conflict-free, and 132*4B = 528B keeps 16B alignment per k-row.
// M, N, K must be multiples of 128/128/8 (true here: 8192 x {3072,1024} x 1024).
// ---------------------------------------------------------------------------
__global__ __launch_bounds__(256, 2)
void sgemm_tn_bias(const float* __restrict__ A,
                   const float* __restrict__ B,
                   const float* __restrict__ bias,
                   float* __restrict__ C,
                   int M, int N, int K)
{
    constexpr int BM = 128, BN = 128, BK = 8, PAD = 4;
    __shared__ __align__(16) float As[BK][BM + PAD];
    __shared__ __align__(16) float Bs[BK][BN + PAD];

    const int tid = threadIdx.x;          // 0..255
    const int bm  = blockIdx.y * BM;
    const int bn  = blockIdx.x * BN;

    // Global-load mapping: 256 threads x 1 float4 covers the 128x8 tile.
    const int lrow = tid >> 1;            // 0..127
    const int lkc  = (tid & 1) * 4;       // 0 or 4

    // Compute mapping: 16x16 thread grid, split 4+4 microtile (conflict-free LDS.128)
    const int tx = tid & 15;
    const int ty = tid >> 4;

    const float* Ap = A + (size_t)(bm + lrow) * K + lkc;
    const float* Bp = B + (size_t)(bn + lrow) * K + lkc;

    float acc[8][8];
#pragma unroll
    for (int i = 0; i < 8; i++)
#pragma unroll
        for (int j = 0; j < 8; j++) acc[i][j] = 0.f;

    for (int k0 = 0; k0 < K; k0 += BK) {
        // Issue global loads before waiting on previous compute.
        const float4 av = *(const float4*)(Ap + k0);
        const float4 bv = *(const float4*)(Bp + k0);
        __syncthreads();
        As[lkc + 0][lrow] = av.x;
        As[lkc + 1][lrow] = av.y;
        As[lkc + 2][lrow] = av.z;
        As[lkc + 3][lrow] = av.w;
        Bs[lkc + 0][lrow] = bv.x;
        Bs[lkc + 1][lrow] = bv.y;
        Bs[lkc + 2][lrow] = bv.z;
        Bs[lkc + 3][lrow] = bv.w;
        __syncthreads();

#pragma unroll
        for (int kk = 0; kk < BK; kk++) {
            const float4 a0 = *(const float4*)(&As[kk][ty * 4]);
            const float4 a1 = *(const float4*)(&As[kk][64 + ty * 4]);
            const float4 b0 = *(const float4*)(&Bs[kk][tx * 4]);
            const float4 b1 = *(const float4*)(&Bs[kk][64 + tx * 4]);
            const float ra[8] = {a0.x, a0.y, a0.z, a0.w, a1.x, a1.y, a1.z, a1.w};
            const float rb[8] = {b0.x, b0.y, b0.z, b0.w, b1.x, b1.y, b1.z, b1.w};
#pragma unroll
            for (int i = 0; i < 8; i++)
#pragma unroll
                for (int j = 0; j < 8; j++)
                    acc[i][j] = fmaf(ra[i], rb[j], acc[i][j]);
        }
    }

    // Epilogue: rows {bm + rg*64 + ty*4 + i}, cols {bn + cg*64 + tx*4 + j}
#pragma unroll
    for (int rg = 0; rg < 2; rg++) {
#pragma unroll
        for (int i = 0; i < 4; i++) {
            const int r = bm + rg * 64 + ty * 4 + i;
#pragma unroll
            for (int cg = 0; cg < 2; cg++) {
                const int c = bn + cg * 64 + tx * 4;
                float4 o;
                o.x = acc[rg * 4 + i][cg * 4 + 0] + bias[c + 0];
                o.y = acc[rg * 4 + i][cg * 4 + 1] + bias[c + 1];
                o.z = acc[rg * 4 + i][cg * 4 + 2] + bias[c + 2];
                o.w = acc[rg * 4 + i][cg * 4 + 3] + bias[c + 3];
                *(float4*)(C + (size_t)r * N + c) = o;
            }
        }
    }
}

// ---------------------------------------------------------------------------
// Banded attention: one warp per (b, t, h). Each query attends to keys in
// [t-4, t+4] (9 slots). qkv layout: row bt = b*T+t, 3072 floats:
// [ q(h*64+d) | 1024 + k | 2048 + v ]. Output att[bt*1024 + h*64 + d].
// Lane owns 2 of the 64 head dims; dot products via full-warp shfl reduce.
// ---------------------------------------------------------------------------
__global__ __launch_bounds__(256)
void focal_attn(const float* __restrict__ qkv, float* __restrict__ out)
{
    const int warp = threadIdx.x >> 5;
    const int lane = threadIdx.x & 31;
    const int gw = blockIdx.x * 8 + warp;     // 0 .. B*T*H-1
    const int h  = gw & (HEADS - 1);
    const int bt = gw >> 4;                   // 0..8191
    const int t  = bt & (TLEN - 1);
    const int b  = bt >> 11;                  // TLEN = 2048 = 2^11

    const size_t row_stride = 3 * DMODEL;     // 3072
    const int doff = h * HDIM + lane * 2;

    const float2 q = *(const float2*)(qkv + (size_t)bt * row_stride + doff);

    // Scores over the 9-wide window (uniform branches per warp: t is warp-uniform)
    float s[9];
#pragma unroll
    for (int jj = 0; jj < 9; jj++) {
        const int j = t - RAD + jj;
        float val = -INFINITY;
        if (j >= 0 && j < TLEN) {
            const float2 kv = *(const float2*)(
                qkv + (size_t)(b * TLEN + j) * row_stride + DMODEL + doff);
            float p = q.x * kv.x + q.y * kv.y;
#pragma unroll
            for (int o = 16; o > 0; o >>= 1)
                p += __shfl_xor_sync(0xffffffffu, p, o);
            val = p * 0.125f;                 // hd^-0.5 = 1/8
        }
        s[jj] = val;
    }

    float m = s[0];
#pragma unroll
    for (int jj = 1; jj < 9; jj++) m = fmaxf(m, s[jj]);

    float p[9];
    float psum = 0.f;
#pragma unroll
    for (int jj = 0; jj < 9; jj++) {
        p[jj] = (s[jj] == -INFINITY) ? 0.f : expf(s[jj] - m);
        psum += p[jj];
    }
    const float inv = 1.f / psum;

    float2 acc = make_float2(0.f, 0.f);
#pragma unroll
    for (int jj = 0; jj < 9; jj++) {
        const int j = t - RAD + jj;
        if (j >= 0 && j < TLEN) {
            const float2 vv = *(const float2*)(
                qkv + (size_t)(b * TLEN + j) * row_stride + 2 * DMODEL + doff);
            acc.x = fmaf(p[jj], vv.x, acc.x);
            acc.y = fmaf(p[jj], vv.y, acc.y);
        }
    }
    acc.x *= inv;
    acc.y *= inv;

    *(float2*)(out + (size_t)bt * DMODEL + doff) = acc;
}

// ---------------------------------------------------------------------------
// Launch: QKV GEMM -> banded attention -> output projection GEMM
// ---------------------------------------------------------------------------
extern "C" void kernel_launch(void* const* d_in, const int* in_sizes, int n_in,
                              void* d_out, int out_size)
{
    const float* x      = (const float*)d_in[0];
    const float* w_qkv  = (const float*)d_in[1];
    const float* b_qkv  = (const float*)d_in[2];
    const float* w_proj = (const float*)d_in[3];
    const float* b_proj = (const float*)d_in[4];
    float* out = (float*)d_out;

    float *qkv, *att;
    cudaGetSymbolAddress((void**)&qkv, g_qkv);
    cudaGetSymbolAddress((void**)&att, g_att);

    const dim3 blk(256);

    // GEMM1: qkv[8192,3072] = x[8192,1024] @ w_qkv[3072,1024]^T + b_qkv
    {
        dim3 grid(3 * DMODEL / 128, MROWS / 128);   // 24 x 64
        sgemm_tn_bias<<<grid, blk>>>(x, w_qkv, b_qkv, qkv, MROWS, 3 * DMODEL, DMODEL);
    }

    // Attention: B*T*H warps = 131072 -> 16384 blocks of 8 warps
    {
        const int total_warps = BSZ * TLEN * HEADS;
        focal_attn<<<total_warps / 8, 256>>>(qkv, att);
    }

    // GEMM2: out[8192,1024] = att[8192,1024] @ w_proj[1024,1024]^T + b_proj
    {
        dim3 grid(DMODEL / 128, MROWS / 128);       // 8 x 64
        sgemm_tn_bias<<<grid, blk>>>(att, w_proj, b_proj, out, MROWS, DMODEL, DMODEL);
    }
}

// round 7
// speedup vs baseline: 1.8665x; 1.8665x over previous
#include <cuda_runtime.h>
#include <cuda_bf16.h>
#include <math.h>
#include <stdint.h>

// Problem constants (fixed per reference)
#define BSZ    4
#define TLEN   2048
#define DMODEL 1024
#define HEADS  16
#define HDIM   64
#define RAD    4
#define MROWS  (BSZ * TLEN)   // 8192

// ---------------------------------------------------------------------------
// Scratch (__device__ globals; no cudaMalloc allowed)
// ---------------------------------------------------------------------------
__device__ __align__(16) float g_qkv[(size_t)MROWS * 3 * DMODEL];          // 96 MB fp32
__device__ __align__(16) __nv_bfloat16 g_x_hi[(size_t)MROWS * DMODEL];
__device__ __align__(16) __nv_bfloat16 g_x_lo[(size_t)MROWS * DMODEL];
__device__ __align__(16) __nv_bfloat16 g_wq_hi[(size_t)3 * DMODEL * DMODEL];
__device__ __align__(16) __nv_bfloat16 g_wq_lo[(size_t)3 * DMODEL * DMODEL];
__device__ __align__(16) __nv_bfloat16 g_wp_hi[(size_t)DMODEL * DMODEL];
__device__ __align__(16) __nv_bfloat16 g_wp_lo[(size_t)DMODEL * DMODEL];
__device__ __align__(16) __nv_bfloat16 g_att_hi[(size_t)MROWS * DMODEL];
__device__ __align__(16) __nv_bfloat16 g_att_lo[(size_t)MROWS * DMODEL];

// ---------------------------------------------------------------------------
// PTX helpers
// ---------------------------------------------------------------------------
__device__ __forceinline__ void cp16(uint32_t dst, const void* src) {
    asm volatile("cp.async.cg.shared.global [%0], [%1], 16;" :: "r"(dst), "l"(src));
}
__device__ __forceinline__ void cp_commit() {
    asm volatile("cp.async.commit_group;" ::: "memory");
}
template <int N>
__device__ __forceinline__ void cp_wait() {
    asm volatile("cp.async.wait_group %0;" :: "n"(N) : "memory");
}
__device__ __forceinline__ void ldsm4(uint32_t* r, uint32_t addr) {
    asm volatile("ldmatrix.sync.aligned.m8n8.x4.shared.b16 {%0,%1,%2,%3}, [%4];"
                 : "=r"(r[0]), "=r"(r[1]), "=r"(r[2]), "=r"(r[3]) : "r"(addr));
}
__device__ __forceinline__ void mma16816(float* d, const uint32_t* a,
                                         uint32_t b0, uint32_t b1) {
    asm volatile(
        "mma.sync.aligned.m16n8k16.row.col.f32.bf16.bf16.f32 "
        "{%0,%1,%2,%3},{%4,%5,%6,%7},{%8,%9},{%0,%1,%2,%3};"
        : "+f"(d[0]), "+f"(d[1]), "+f"(d[2]), "+f"(d[3])
        : "r"(a[0]), "r"(a[1]), "r"(a[2]), "r"(a[3]), "r"(b0), "r"(b1));
}

// XOR swizzle: 16B chunk c within 64B row, rotated so 8 consecutive rows map to
// 8 distinct 16B bank-groups mod 128B -> conflict-free LDSM and STS.
#define SWZ(row, c) (((c) ^ (((row) >> 1) & 3)))

// ---------------------------------------------------------------------------
// bf16x3 split: fp32 -> (hi, lo) bf16 planes, 4 elems/thread
// ---------------------------------------------------------------------------
__global__ void split4(const float4* __restrict__ in,
                       __nv_bfloat162* __restrict__ hi,
                       __nv_bfloat162* __restrict__ lo, int n4)
{
    int i = blockIdx.x * blockDim.x + threadIdx.x;
    if (i >= n4) return;
    float4 v = in[i];
    __nv_bfloat16 hx = __float2bfloat16(v.x), hy = __float2bfloat16(v.y);
    __nv_bfloat16 hz = __float2bfloat16(v.z), hw = __float2bfloat16(v.w);
    __nv_bfloat162 h0; h0.x = hx; h0.y = hy;
    __nv_bfloat162 h1; h1.x = hz; h1.y = hw;
    __nv_bfloat162 l0, l1;
    l0.x = __float2bfloat16(v.x - __bfloat162float(hx));
    l0.y = __float2bfloat16(v.y - __bfloat162float(hy));
    l1.x = __float2bfloat16(v.z - __bfloat162float(hz));
    l1.y = __float2bfloat16(v.w - __bfloat162float(hw));
    hi[2 * i]     = h0;  hi[2 * i + 1] = h1;
    lo[2 * i]     = l0;  lo[2 * i + 1] = l1;
}

// ---------------------------------------------------------------------------
// Tensor-core GEMM (TN): C[M,N] = A[M,K] @ B[N,K]^T + bias, fp32-accurate via
// bf16x3: D += Ahi*Bhi + Ahi*Blo + Alo*Bhi (fp32 accumulate in HMMA).
// CTA tile 128x128x32, 8 warps (2x4) of 64x32, double-buffered cp.async smem.
// smem per stage: 4 planes (Ahi,Alo,Bhi,Blo) x 128x32 bf16 = 32KB; 2 stages.
// Requires M%128==0, N%128==0, K%32==0 (true: 8192 x {3072,1024} x 1024).
// ---------------------------------------------------------------------------
__global__ __launch_bounds__(256)
void gemm_bf16x3(const __nv_bfloat16* __restrict__ Ahi,
                 const __nv_bfloat16* __restrict__ Alo,
                 const __nv_bfloat16* __restrict__ Bhi,
                 const __nv_bfloat16* __restrict__ Blo,
                 const float* __restrict__ bias,
                 float* __restrict__ C,
                 int M, int N, int K)
{
    extern __shared__ char smem[];
    const uint32_t sbase = (uint32_t)__cvta_generic_to_shared(smem);

    const int tid  = threadIdx.x;
    const int lane = tid & 31;
    const int warp = tid >> 5;
    const int bm = blockIdx.y * 128;
    const int bn = blockIdx.x * 128;
    const int wm = (warp >> 2) * 64;   // warp row offset in tile
    const int wn = (warp & 3) * 32;    // warp col offset in tile

    // ---- cp.async mapping: thread covers row tid>>1, chunks {c0, c0+1} ----
    const int lrow = tid >> 1;
    const int c0   = (tid & 1) * 2;
    const __nv_bfloat16* srcs[4] = {
        Ahi + (size_t)(bm + lrow) * K,
        Alo + (size_t)(bm + lrow) * K,
        Bhi + (size_t)(bn + lrow) * K,
        Blo + (size_t)(bn + lrow) * K
    };
    const uint32_t sd0 = lrow * 64 + SWZ(lrow, c0) * 16;
    const uint32_t sd1 = lrow * 64 + SWZ(lrow, c0 + 1) * 16;

    auto load_stage = [&](int s, int k0) {
        const uint32_t base = sbase + s * 32768;
#pragma unroll
        for (int p = 0; p < 4; p++) {
            const __nv_bfloat16* g = srcs[p] + k0;
            cp16(base + p * 8192 + sd0, g + c0 * 8);
            cp16(base + p * 8192 + sd1, g + (c0 + 1) * 8);
        }
        cp_commit();
    };

    float acc[4][4][4];
#pragma unroll
    for (int i = 0; i < 4; i++)
#pragma unroll
        for (int j = 0; j < 4; j++)
#pragma unroll
            for (int k = 0; k < 4; k++) acc[i][j][k] = 0.f;

    const int NIT = K >> 5;
    load_stage(0, 0);

    const int r16 = lane & 15;
    const int khalf = lane >> 4;

#pragma unroll 1
    for (int it = 0; it < NIT; it++) {
        if (it + 1 < NIT) { load_stage((it + 1) & 1, (it + 1) * 32); cp_wait<1>(); }
        else              { cp_wait<0>(); }
        __syncthreads();

        const uint32_t stbase = sbase + (it & 1) * 32768;
#pragma unroll
        for (int kk = 0; kk < 32; kk += 16) {
            uint32_t ah[4][4], al[4][4], bh[2][4], bl[2][4];
            const int kc = (kk >> 3) + khalf;   // 16B chunk index 0..3
#pragma unroll
            for (int mb = 0; mb < 4; mb++) {
                const int row = wm + mb * 16 + r16;
                const uint32_t off = row * 64 + SWZ(row, kc) * 16;
                ldsm4(ah[mb], stbase + off);           // A_hi plane
                ldsm4(al[mb], stbase + 8192 + off);    // A_lo plane
            }
#pragma unroll
            for (int ng = 0; ng < 2; ng++) {
                const int row = wn + ng * 16 + r16;
                const uint32_t off = row * 64 + SWZ(row, kc) * 16;
                ldsm4(bh[ng], stbase + 16384 + off);   // B_hi plane
                ldsm4(bl[ng], stbase + 24576 + off);   // B_lo plane
            }
#pragma unroll
            for (int mb = 0; mb < 4; mb++)
#pragma unroll
                for (int nb = 0; nb < 4; nb++) {
                    const int ng = nb >> 1, j = nb & 1;
                    mma16816(acc[mb][nb], ah[mb], bh[ng][j], bh[ng][2 + j]);
                    mma16816(acc[mb][nb], ah[mb], bl[ng][j], bl[ng][2 + j]);
                    mma16816(acc[mb][nb], al[mb], bh[ng][j], bh[ng][2 + j]);
                }
        }
        __syncthreads();
    }

    // ---- Epilogue: bias add, fp32 stores ----
    const int g  = lane >> 2;
    const int t2 = (lane & 3) * 2;
#pragma unroll
    for (int nb = 0; nb < 4; nb++) {
        const int col = bn + wn + nb * 8 + t2;
        const float bx = bias[col], by = bias[col + 1];
#pragma unroll
        for (int mb = 0; mb < 4; mb++) {
            const int row = bm + wm + mb * 16 + g;
            float2 v0 = make_float2(acc[mb][nb][0] + bx, acc[mb][nb][1] + by);
            float2 v1 = make_float2(acc[mb][nb][2] + bx, acc[mb][nb][3] + by);
            *(float2*)(C + (size_t)row * N + col)       = v0;
            *(float2*)(C + (size_t)(row + 8) * N + col) = v1;
        }
    }
}

// ---------------------------------------------------------------------------
// Banded attention: one warp per (b,t,h), 9-key window, warp-shfl reductions.
// Reads fp32 qkv [bt][ q | D+k | 2D+v ]; writes output directly as bf16 hi/lo
// planes (feeding GEMM2 without an fp32 round trip).
// ---------------------------------------------------------------------------
__global__ __launch_bounds__(256)
void focal_attn(const float* __restrict__ qkv,
                __nv_bfloat16* __restrict__ out_hi,
                __nv_bfloat16* __restrict__ out_lo)
{
    const int warp = threadIdx.x >> 5;
    const int lane = threadIdx.x & 31;
    const int gw = blockIdx.x * 8 + warp;     // 0 .. B*T*H-1
    const int h  = gw & (HEADS - 1);
    const int bt = gw >> 4;
    const int t  = bt & (TLEN - 1);
    const int b  = bt >> 11;

    const size_t row_stride = 3 * DMODEL;
    const int doff = h * HDIM + lane * 2;

    const float2 q = *(const float2*)(qkv + (size_t)bt * row_stride + doff);

    float s[9];
#pragma unroll
    for (int jj = 0; jj < 9; jj++) {
        const int j = t - RAD + jj;
        float val = -INFINITY;
        if (j >= 0 && j < TLEN) {
            const float2 kv = *(const float2*)(
                qkv + (size_t)(b * TLEN + j) * row_stride + DMODEL + doff);
            float p = q.x * kv.x + q.y * kv.y;
#pragma unroll
            for (int o = 16; o > 0; o >>= 1)
                p += __shfl_xor_sync(0xffffffffu, p, o);
            val = p * 0.125f;   // hd^-0.5
        }
        s[jj] = val;
    }

    float m = s[0];
#pragma unroll
    for (int jj = 1; jj < 9; jj++) m = fmaxf(m, s[jj]);

    float p[9], psum = 0.f;
#pragma unroll
    for (int jj = 0; jj < 9; jj++) {
        p[jj] = (s[jj] == -INFINITY) ? 0.f : expf(s[jj] - m);
        psum += p[jj];
    }
    const float inv = 1.f / psum;

    float2 acc = make_float2(0.f, 0.f);
#pragma unroll
    for (int jj = 0; jj < 9; jj++) {
        const int j = t - RAD + jj;
        if (j >= 0 && j < TLEN) {
            const float2 vv = *(const float2*)(
                qkv + (size_t)(b * TLEN + j) * row_stride + 2 * DMODEL + doff);
            acc.x = fmaf(p[jj], vv.x, acc.x);
            acc.y = fmaf(p[jj], vv.y, acc.y);
        }
    }
    acc.x *= inv;
    acc.y *= inv;

    const __nv_bfloat16 hx = __float2bfloat16(acc.x);
    const __nv_bfloat16 hy = __float2bfloat16(acc.y);
    __nv_bfloat162 hp; hp.x = hx; hp.y = hy;
    __nv_bfloat162 lp;
    lp.x = __float2bfloat16(acc.x - __bfloat162float(hx));
    lp.y = __float2bfloat16(acc.y - __bfloat162float(hy));
    *(__nv_bfloat162*)(out_hi + (size_t)bt * DMODEL + doff) = hp;
    *(__nv_bfloat162*)(out_lo + (size_t)bt * DMODEL + doff) = lp;
}

// ---------------------------------------------------------------------------
// Launch: split inputs -> QKV GEMM (tensor) -> attention -> proj GEMM (tensor)
// ---------------------------------------------------------------------------
extern "C" void kernel_launch(void* const* d_in, const int* in_sizes, int n_in,
                              void* d_out, int out_size)
{
    const float* x      = (const float*)d_in[0];
    const float* w_qkv  = (const float*)d_in[1];
    const float* b_qkv  = (const float*)d_in[2];
    const float* w_proj = (const float*)d_in[3];
    const float* b_proj = (const float*)d_in[4];
    float* out = (float*)d_out;

    float *qkv;
    __nv_bfloat16 *xhi, *xlo, *wqhi, *wqlo, *wphi, *wplo, *athi, *atlo;
    cudaGetSymbolAddress((void**)&qkv,  g_qkv);
    cudaGetSymbolAddress((void**)&xhi,  g_x_hi);
    cudaGetSymbolAddress((void**)&xlo,  g_x_lo);
    cudaGetSymbolAddress((void**)&wqhi, g_wq_hi);
    cudaGetSymbolAddress((void**)&wqlo, g_wq_lo);
    cudaGetSymbolAddress((void**)&wphi, g_wp_hi);
    cudaGetSymbolAddress((void**)&wplo, g_wp_lo);
    cudaGetSymbolAddress((void**)&athi, g_att_hi);
    cudaGetSymbolAddress((void**)&atlo, g_att_lo);

    cudaFuncSetAttribute(gemm_bf16x3,
                         cudaFuncAttributeMaxDynamicSharedMemorySize, 65536);

    // Split fp32 inputs into bf16 hi/lo planes
    {
        int n4 = MROWS * DMODEL / 4;
        split4<<<(n4 + 255) / 256, 256>>>((const float4*)x,
                                          (__nv_bfloat162*)xhi, (__nv_bfloat162*)xlo, n4);
        n4 = 3 * DMODEL * DMODEL / 4;
        split4<<<(n4 + 255) / 256, 256>>>((const float4*)w_qkv,
                                          (__nv_bfloat162*)wqhi, (__nv_bfloat162*)wqlo, n4);
        n4 = DMODEL * DMODEL / 4;
        split4<<<(n4 + 255) / 256, 256>>>((const float4*)w_proj,
                                          (__nv_bfloat162*)wphi, (__nv_bfloat162*)wplo, n4);
    }

    // GEMM1: qkv[8192,3072] = x @ w_qkv^T + b_qkv
    {
        dim3 grid(3 * DMODEL / 128, MROWS / 128);   // 24 x 64
        gemm_bf16x3<<<grid, 256, 65536>>>(xhi, xlo, wqhi, wqlo, b_qkv, qkv,
                                          MROWS, 3 * DMODEL, DMODEL);
    }

    // Attention: B*T*H warps
    {
        const int total_warps = BSZ * TLEN * HEADS;
        focal_attn<<<total_warps / 8, 256>>>(qkv, athi, atlo);
    }

    // GEMM2: out[8192,1024] = att @ w_proj^T + b_proj
    {
        dim3 grid(DMODEL / 128, MROWS / 128);       // 8 x 64
        gemm_bf16x3<<<grid, 256, 65536>>>(athi, atlo, wphi, wplo, b_proj, out,
                                          MROWS, DMODEL, DMODEL);
    }
}

// round 9
// speedup vs baseline: 1.9037x; 1.0199x over previous
#include <cuda_runtime.h>
#include <cuda_bf16.h>
#include <math.h>
#include <stdint.h>

// Problem constants (fixed per reference)
#define BSZ    4
#define TLEN   2048
#define DMODEL 1024
#define HEADS  16
#define HDIM   64
#define RAD    4
#define MROWS  (BSZ * TLEN)   // 8192

// ---------------------------------------------------------------------------
// Scratch (__device__ globals; no cudaMalloc allowed)
// ---------------------------------------------------------------------------
__device__ __align__(16) float g_qkv[(size_t)MROWS * 3 * DMODEL];
__device__ __align__(16) __nv_bfloat16 g_x_hi[(size_t)MROWS * DMODEL];
__device__ __align__(16) __nv_bfloat16 g_x_lo[(size_t)MROWS * DMODEL];
__device__ __align__(16) __nv_bfloat16 g_wq_hi[(size_t)3 * DMODEL * DMODEL];
__device__ __align__(16) __nv_bfloat16 g_wq_lo[(size_t)3 * DMODEL * DMODEL];
__device__ __align__(16) __nv_bfloat16 g_wp_hi[(size_t)DMODEL * DMODEL];
__device__ __align__(16) __nv_bfloat16 g_wp_lo[(size_t)DMODEL * DMODEL];
__device__ __align__(16) __nv_bfloat16 g_att_hi[(size_t)MROWS * DMODEL];
__device__ __align__(16) __nv_bfloat16 g_att_lo[(size_t)MROWS * DMODEL];

// ---------------------------------------------------------------------------
// PTX helpers
// ---------------------------------------------------------------------------
__device__ __forceinline__ void cp16(uint32_t dst, const void* src) {
    asm volatile("cp.async.cg.shared.global [%0], [%1], 16;" :: "r"(dst), "l"(src));
}
__device__ __forceinline__ void cp_commit() {
    asm volatile("cp.async.commit_group;" ::: "memory");
}
template <int N>
__device__ __forceinline__ void cp_wait() {
    asm volatile("cp.async.wait_group %0;" :: "n"(N) : "memory");
}
__device__ __forceinline__ void ldsm4(uint32_t* r, uint32_t addr) {
    asm volatile("ldmatrix.sync.aligned.m8n8.x4.shared.b16 {%0,%1,%2,%3}, [%4];"
                 : "=r"(r[0]), "=r"(r[1]), "=r"(r[2]), "=r"(r[3]) : "r"(addr));
}
__device__ __forceinline__ void mma16816(float* d, const uint32_t* a,
                                         uint32_t b0, uint32_t b1) {
    asm volatile(
        "mma.sync.aligned.m16n8k16.row.col.f32.bf16.bf16.f32 "
        "{%0,%1,%2,%3},{%4,%5,%6,%7},{%8,%9},{%0,%1,%2,%3};"
        : "+f"(d[0]), "+f"(d[1]), "+f"(d[2]), "+f"(d[3])
        : "r"(a[0]), "r"(a[1]), "r"(a[2]), "r"(a[3]), "r"(b0), "r"(b1));
}

// XOR swizzle: 16B chunk c within 64B row, rotated so 8 consecutive rows map to
// 8 distinct 16B bank-groups mod 128B -> conflict-free LDSM and STS.
#define SWZ(row, c) (((c) ^ (((row) >> 1) & 3)))

// ---------------------------------------------------------------------------
// bf16x3 split: fp32 -> (hi, lo) bf16 planes, 4 elems/thread
// ---------------------------------------------------------------------------
__global__ void split4(const float4* __restrict__ in,
                       __nv_bfloat162* __restrict__ hi,
                       __nv_bfloat162* __restrict__ lo, int n4)
{
    int i = blockIdx.x * blockDim.x + threadIdx.x;
    if (i >= n4) return;
    float4 v = in[i];
    __nv_bfloat16 hx = __float2bfloat16(v.x), hy = __float2bfloat16(v.y);
    __nv_bfloat16 hz = __float2bfloat16(v.z), hw = __float2bfloat16(v.w);
    __nv_bfloat162 h0; h0.x = hx; h0.y = hy;
    __nv_bfloat162 h1; h1.x = hz; h1.y = hw;
    __nv_bfloat162 l0, l1;
    l0.x = __float2bfloat16(v.x - __bfloat162float(hx));
    l0.y = __float2bfloat16(v.y - __bfloat162float(hy));
    l1.x = __float2bfloat16(v.z - __bfloat162float(hz));
    l1.y = __float2bfloat16(v.w - __bfloat162float(hw));
    hi[2 * i]     = h0;  hi[2 * i + 1] = h1;
    lo[2 * i]     = l0;  lo[2 * i + 1] = l1;
}

// ---------------------------------------------------------------------------
// Tensor-core GEMM (TN): C[M,N] = A[M,K] @ B[N,K]^T + bias, fp32-accurate via
// bf16x3: D += Ahi*Bhi + Ahi*Blo + Alo*Bhi (fp32 accumulate in HMMA).
// CTA tile 128x128x32, 8 warps (2x4) of 64x32.
// 3-stage cp.async pipeline, prefetch distance 2 (32KB/stage, 96KB total),
// __launch_bounds__(256,2) -> 2 CTAs/SM (192KB smem, <=128 regs).
// Requires M%128==0, N%128==0, K%32==0 (true: 8192 x {3072,1024} x 1024).
// ---------------------------------------------------------------------------
#define STAGE_BYTES 32768
#define NSTAGE 3
#define GEMM_SMEM (NSTAGE * STAGE_BYTES)

__global__ __launch_bounds__(256, 2)
void gemm_bf16x3(const __nv_bfloat16* __restrict__ Ahi,
                 const __nv_bfloat16* __restrict__ Alo,
                 const __nv_bfloat16* __restrict__ Bhi,
                 const __nv_bfloat16* __restrict__ Blo,
                 const float* __restrict__ bias,
                 float* __restrict__ C,
                 int M, int N, int K)
{
    extern __shared__ char smem[];
    const uint32_t sbase = (uint32_t)__cvta_generic_to_shared(smem);

    const int tid  = threadIdx.x;
    const int lane = tid & 31;
    const int warp = tid >> 5;
    const int bm = blockIdx.y * 128;
    const int bn = blockIdx.x * 128;
    const int wm = (warp >> 2) * 64;   // warp row offset in tile
    const int wn = (warp & 3) * 32;    // warp col offset in tile

    // ---- cp.async mapping: thread covers row tid>>1, chunks {c0, c0+1} ----
    const int lrow = tid >> 1;
    const int c0   = (tid & 1) * 2;
    const __nv_bfloat16* srcs[4] = {
        Ahi + (size_t)(bm + lrow) * K,
        Alo + (size_t)(bm + lrow) * K,
        Bhi + (size_t)(bn + lrow) * K,
        Blo + (size_t)(bn + lrow) * K
    };
    const uint32_t sd0 = lrow * 64 + SWZ(lrow, c0) * 16;
    const uint32_t sd1 = lrow * 64 + SWZ(lrow, c0 + 1) * 16;

    auto load_stage = [&](int s, int k0) {
        const uint32_t base = sbase + s * STAGE_BYTES;
#pragma unroll
        for (int p = 0; p < 4; p++) {
            const __nv_bfloat16* g = srcs[p] + k0;
            cp16(base + p * 8192 + sd0, g + c0 * 8);
            cp16(base + p * 8192 + sd1, g + (c0 + 1) * 8);
        }
        cp_commit();
    };

    float acc[4][4][4];
#pragma unroll
    for (int i = 0; i < 4; i++)
#pragma unroll
        for (int j = 0; j < 4; j++)
#pragma unroll
            for (int k = 0; k < 4; k++) acc[i][j][k] = 0.f;

    const int NIT = K >> 5;            // 32
    load_stage(0, 0);
    load_stage(1, 32);

    const int r16 = lane & 15;
    const int khalf = lane >> 4;

#pragma unroll 1
    for (int it = 0; it < NIT; it++) {
        // Stage `it` must be complete; allow the younger group to stay pending.
        if (it + 1 < NIT) cp_wait<1>(); else cp_wait<0>();
        __syncthreads();   // also guarantees everyone finished compute(it-1)

        // Prefetch distance 2: overwrite buffer (it-1)%3, now provably idle.
        if (it + 2 < NIT) {
            int s2 = it + 2;
            s2 -= (s2 / 3) * 3;
            load_stage(s2, (it + 2) * 32);
        }

        const int s = it - (it / 3) * 3;
        const uint32_t stbase = sbase + s * STAGE_BYTES;
#pragma unroll
        for (int kk = 0; kk < 32; kk += 16) {
            uint32_t ah[4][4], al[4][4], bh[2][4], bl[2][4];
            const int kc = (kk >> 3) + khalf;   // 16B chunk index 0..3
#pragma unroll
            for (int mb = 0; mb < 4; mb++) {
                const int row = wm + mb * 16 + r16;
                const uint32_t off = row * 64 + SWZ(row, kc) * 16;
                ldsm4(ah[mb], stbase + off);           // A_hi plane
                ldsm4(al[mb], stbase + 8192 + off);    // A_lo plane
            }
#pragma unroll
            for (int ng = 0; ng < 2; ng++) {
                const int row = wn + ng * 16 + r16;
                const uint32_t off = row * 64 + SWZ(row, kc) * 16;
                ldsm4(bh[ng], stbase + 16384 + off);   // B_hi plane
                ldsm4(bl[ng], stbase + 24576 + off);   // B_lo plane
            }
#pragma unroll
            for (int mb = 0; mb < 4; mb++)
#pragma unroll
                for (int nb = 0; nb < 4; nb++) {
                    const int ng = nb >> 1, j = nb & 1;
                    mma16816(acc[mb][nb], ah[mb], bh[ng][j], bh[ng][2 + j]);
                    mma16816(acc[mb][nb], ah[mb], bl[ng][j], bl[ng][2 + j]);
                    mma16816(acc[mb][nb], al[mb], bh[ng][j], bh[ng][2 + j]);
                }
        }
    }

    // ---- Epilogue: bias add, fp32 stores ----
    const int g  = lane >> 2;
    const int t2 = (lane & 3) * 2;
#pragma unroll
    for (int nb = 0; nb < 4; nb++) {
        const int col = bn + wn + nb * 8 + t2;
        const float bx = __ldg(bias + col), by = __ldg(bias + col + 1);
#pragma unroll
        for (int mb = 0; mb < 4; mb++) {
            const int row = bm + wm + mb * 16 + g;
            float2 v0 = make_float2(acc[mb][nb][0] + bx, acc[mb][nb][1] + by);
            float2 v1 = make_float2(acc[mb][nb][2] + bx, acc[mb][nb][3] + by);
            *(float2*)(C + (size_t)row * N + col)       = v0;
            *(float2*)(C + (size_t)(row + 8) * N + col) = v1;
        }
    }
}

// ---------------------------------------------------------------------------
// Banded attention: one warp per (b,t,h), 9-key window, warp-shfl reductions.
// Reads fp32 qkv [bt][ q | D+k | 2D+v ]; writes output directly as bf16 hi/lo
// planes (feeding GEMM2 without an fp32 round trip).
// ---------------------------------------------------------------------------
__global__ __launch_bounds__(256)
void focal_attn(const float* __restrict__ qkv,
                __nv_bfloat16* __restrict__ out_hi,
                __nv_bfloat16* __restrict__ out_lo)
{
    const int warp = threadIdx.x >> 5;
    const int lane = threadIdx.x & 31;
    const int gw = blockIdx.x * 8 + warp;     // 0 .. B*T*H-1
    const int h  = gw & (HEADS - 1);
    const int bt = gw >> 4;
    const int t  = bt & (TLEN - 1);
    const int b  = bt >> 11;

    const size_t row_stride = 3 * DMODEL;
    const int doff = h * HDIM + lane * 2;

    const float2 q = *(const float2*)(qkv + (size_t)bt * row_stride + doff);

    float s[9];
#pragma unroll
    for (int jj = 0; jj < 9; jj++) {
        const int j = t - RAD + jj;
        float val = -INFINITY;
        if (j >= 0 && j < TLEN) {
            const float2 kv = *(const float2*)(
                qkv + (size_t)(b * TLEN + j) * row_stride + DMODEL + doff);
            float p = q.x * kv.x + q.y * kv.y;
#pragma unroll
            for (int o = 16; o > 0; o >>= 1)
                p += __shfl_xor_sync(0xffffffffu, p, o);
            val = p * 0.125f;   // hd^-0.5
        }
        s[jj] = val;
    }

    float m = s[0];
#pragma unroll
    for (int jj = 1; jj < 9; jj++) m = fmaxf(m, s[jj]);

    float p[9], psum = 0.f;
#pragma unroll
    for (int jj = 0; jj < 9; jj++) {
        p[jj] = (s[jj] == -INFINITY) ? 0.f : expf(s[jj] - m);
        psum += p[jj];
    }
    const float inv = 1.f / psum;

    float2 acc = make_float2(0.f, 0.f);
#pragma unroll
    for (int jj = 0; jj < 9; jj++) {
        const int j = t - RAD + jj;
        if (j >= 0 && j < TLEN) {
            const float2 vv = *(const float2*)(
                qkv + (size_t)(b * TLEN + j) * row_stride + 2 * DMODEL + doff);
            acc.x = fmaf(p[jj], vv.x, acc.x);
            acc.y = fmaf(p[jj], vv.y, acc.y);
        }
    }
    acc.x *= inv;
    acc.y *= inv;

    const __nv_bfloat16 hx = __float2bfloat16(acc.x);
    const __nv_bfloat16 hy = __float2bfloat16(acc.y);
    __nv_bfloat162 hp; hp.x = hx; hp.y = hy;
    __nv_bfloat162 lp;
    lp.x = __float2bfloat16(acc.x - __bfloat162float(hx));
    lp.y = __float2bfloat16(acc.y - __bfloat162float(hy));
    *(__nv_bfloat162*)(out_hi + (size_t)bt * DMODEL + doff) = hp;
    *(__nv_bfloat162*)(out_lo + (size_t)bt * DMODEL + doff) = lp;
}

// ---------------------------------------------------------------------------
// Launch: split inputs -> QKV GEMM (tensor) -> attention -> proj GEMM (tensor)
// ---------------------------------------------------------------------------
extern "C" void kernel_launch(void* const* d_in, const int* in_sizes, int n_in,
                              void* d_out, int out_size)
{
    const float* x      = (const float*)d_in[0];
    const float* w_qkv  = (const float*)d_in[1];
    const float* b_qkv  = (const float*)d_in[2];
    const float* w_proj = (const float*)d_in[3];
    const float* b_proj = (const float*)d_in[4];
    float* out = (float*)d_out;

    float *qkv;
    __nv_bfloat16 *xhi, *xlo, *wqhi, *wqlo, *wphi, *wplo, *athi, *atlo;
    cudaGetSymbolAddress((void**)&qkv,  g_qkv);
    cudaGetSymbolAddress((void**)&xhi,  g_x_hi);
    cudaGetSymbolAddress((void**)&xlo,  g_x_lo);
    cudaGetSymbolAddress((void**)&wqhi, g_wq_hi);
    cudaGetSymbolAddress((void**)&wqlo, g_wq_lo);
    cudaGetSymbolAddress((void**)&wphi, g_wp_hi);
    cudaGetSymbolAddress((void**)&wplo, g_wp_lo);
    cudaGetSymbolAddress((void**)&athi, g_att_hi);
    cudaGetSymbolAddress((void**)&atlo, g_att_lo);

    cudaFuncSetAttribute(gemm_bf16x3,
                         cudaFuncAttributeMaxDynamicSharedMemorySize, GEMM_SMEM);

    // Split fp32 inputs into bf16 hi/lo planes
    {
        int n4 = MROWS * DMODEL / 4;
        split4<<<(n4 + 255) / 256, 256>>>((const float4*)x,
                                          (__nv_bfloat162*)xhi, (__nv_bfloat162*)xlo, n4);
        n4 = 3 * DMODEL * DMODEL / 4;
        split4<<<(n4 + 255) / 256, 256>>>((const float4*)w_qkv,
                                          (__nv_bfloat162*)wqhi, (__nv_bfloat162*)wqlo, n4);
        n4 = DMODEL * DMODEL / 4;
        split4<<<(n4 + 255) / 256, 256>>>((const float4*)w_proj,
                                          (__nv_bfloat162*)wphi, (__nv_bfloat162*)wplo, n4);
    }

    // GEMM1: qkv[8192,3072] = x @ w_qkv^T + b_qkv
    {
        dim3 grid(3 * DMODEL / 128, MROWS / 128);   // 24 x 64
        gemm_bf16x3<<<grid, 256, GEMM_SMEM>>>(xhi, xlo, wqhi, wqlo, b_qkv, qkv,
                                              MROWS, 3 * DMODEL, DMODEL);
    }

    // Attention: B*T*H warps
    {
        const int total_warps = BSZ * TLEN * HEADS;
        focal_attn<<<total_warps / 8, 256>>>(qkv, athi, atlo);
    }

    // GEMM2: out[8192,1024] = att @ w_proj^T + b_proj
    {
        dim3 grid(DMODEL / 128, MROWS / 128);       // 8 x 64
        gemm_bf16x3<<<grid, 256, GEMM_SMEM>>>(athi, atlo, wphi, wplo, b_proj, out,
                                              MROWS, DMODEL, DMODEL);
    }
}

// round 10
// speedup vs baseline: 1.9374x; 1.0177x over previous
#include <cuda_runtime.h>
#include <cuda_bf16.h>
#include <math.h>
#include <stdint.h>

// Problem constants (fixed per reference)
#define BSZ    4
#define TLEN   2048
#define DMODEL 1024
#define HEADS  16
#define HDIM   64
#define RAD    4
#define MROWS  (BSZ * TLEN)   // 8192

// ---------------------------------------------------------------------------
// Scratch (__device__ globals; no cudaMalloc allowed)
// ---------------------------------------------------------------------------
__device__ __align__(16) float g_qkv[(size_t)MROWS * 3 * DMODEL];
__device__ __align__(16) __nv_bfloat16 g_x_hi[(size_t)MROWS * DMODEL];
__device__ __align__(16) __nv_bfloat16 g_x_lo[(size_t)MROWS * DMODEL];
__device__ __align__(16) __nv_bfloat16 g_wq_hi[(size_t)3 * DMODEL * DMODEL];
__device__ __align__(16) __nv_bfloat16 g_wq_lo[(size_t)3 * DMODEL * DMODEL];
__device__ __align__(16) __nv_bfloat16 g_wp_hi[(size_t)DMODEL * DMODEL];
__device__ __align__(16) __nv_bfloat16 g_wp_lo[(size_t)DMODEL * DMODEL];
__device__ __align__(16) __nv_bfloat16 g_att_hi[(size_t)MROWS * DMODEL];
__device__ __align__(16) __nv_bfloat16 g_att_lo[(size_t)MROWS * DMODEL];

// ---------------------------------------------------------------------------
// PTX helpers
// ---------------------------------------------------------------------------
__device__ __forceinline__ void cp16(uint32_t dst, const void* src) {
    asm volatile("cp.async.cg.shared.global [%0], [%1], 16;" :: "r"(dst), "l"(src));
}
__device__ __forceinline__ void cp_commit() {
    asm volatile("cp.async.commit_group;" ::: "memory");
}
template <int N>
__device__ __forceinline__ void cp_wait() {
    asm volatile("cp.async.wait_group %0;" :: "n"(N) : "memory");
}
__device__ __forceinline__ void ldsm4(uint32_t* r, uint32_t addr) {
    asm volatile("ldmatrix.sync.aligned.m8n8.x4.shared.b16 {%0,%1,%2,%3}, [%4];"
                 : "=r"(r[0]), "=r"(r[1]), "=r"(r[2]), "=r"(r[3]) : "r"(addr));
}
__device__ __forceinline__ void mma16816(float* d, const uint32_t* a,
                                         uint32_t b0, uint32_t b1) {
    asm volatile(
        "mma.sync.aligned.m16n8k16.row.col.f32.bf16.bf16.f32 "
        "{%0,%1,%2,%3},{%4,%5,%6,%7},{%8,%9},{%0,%1,%2,%3};"
        : "+f"(d[0]), "+f"(d[1]), "+f"(d[2]), "+f"(d[3])
        : "r"(a[0]), "r"(a[1]), "r"(a[2]), "r"(a[3]), "r"(b0), "r"(b1));
}

// XOR swizzle: 16B chunk c within 64B row, rotated so 8 consecutive rows map to
// 8 distinct 16B bank-groups mod 128B -> conflict-free LDSM and STS.
#define SWZ(row, c) (((c) ^ (((row) >> 1) & 3)))

// ---------------------------------------------------------------------------
// bf16x3 split: fp32 -> (hi, lo) bf16 planes, 4 elems/thread
// ---------------------------------------------------------------------------
__global__ void split4(const float4* __restrict__ in,
                       __nv_bfloat162* __restrict__ hi,
                       __nv_bfloat162* __restrict__ lo, int n4)
{
    int i = blockIdx.x * blockDim.x + threadIdx.x;
    if (i >= n4) return;
    float4 v = in[i];
    __nv_bfloat16 hx = __float2bfloat16(v.x), hy = __float2bfloat16(v.y);
    __nv_bfloat16 hz = __float2bfloat16(v.z), hw = __float2bfloat16(v.w);
    __nv_bfloat162 h0; h0.x = hx; h0.y = hy;
    __nv_bfloat162 h1; h1.x = hz; h1.y = hw;
    __nv_bfloat162 l0, l1;
    l0.x = __float2bfloat16(v.x - __bfloat162float(hx));
    l0.y = __float2bfloat16(v.y - __bfloat162float(hy));
    l1.x = __float2bfloat16(v.z - __bfloat162float(hz));
    l1.y = __float2bfloat16(v.w - __bfloat162float(hw));
    hi[2 * i]     = h0;  hi[2 * i + 1] = h1;
    lo[2 * i]     = l0;  lo[2 * i + 1] = l1;
}

// ---------------------------------------------------------------------------
// Tensor-core GEMM (TN): C[M,N] = A[M,K] @ B[N,K]^T + bias, fp32-accurate via
// bf16x3: D += Ahi*Bhi + Ahi*Blo + Alo*Bhi (fp32 accumulate in HMMA).
// CTA tile 128x128x32, 8 warps (2x4) of 64x32.
// 3-stage cp.async pipeline (prefetch distance 2), 2 CTAs/SM.
// Anti-convoy: odd warps process kk-halves in reverse order so LDSM and HMMA
// phases interleave across warps instead of lockstepping after the barrier.
// Requires M%128==0, N%128==0, K%32==0 (true: 8192 x {3072,1024} x 1024).
// ---------------------------------------------------------------------------
#define STAGE_BYTES 32768
#define NSTAGE 3
#define GEMM_SMEM (NSTAGE * STAGE_BYTES)

__global__ __launch_bounds__(256, 2)
void gemm_bf16x3(const __nv_bfloat16* __restrict__ Ahi,
                 const __nv_bfloat16* __restrict__ Alo,
                 const __nv_bfloat16* __restrict__ Bhi,
                 const __nv_bfloat16* __restrict__ Blo,
                 const float* __restrict__ bias,
                 float* __restrict__ C,
                 int M, int N, int K)
{
    extern __shared__ char smem[];
    const uint32_t sbase = (uint32_t)__cvta_generic_to_shared(smem);

    const int tid  = threadIdx.x;
    const int lane = tid & 31;
    const int warp = tid >> 5;
    const int bm = blockIdx.y * 128;
    const int bn = blockIdx.x * 128;
    const int wm = (warp >> 2) * 64;   // warp row offset in tile
    const int wn = (warp & 3) * 32;    // warp col offset in tile
    const int whalf = warp & 1;        // kk-order stagger

    // ---- cp.async mapping: thread covers row tid>>1, chunks {c0, c0+1} ----
    const int lrow = tid >> 1;
    const int c0   = (tid & 1) * 2;
    const __nv_bfloat16* srcs[4] = {
        Ahi + (size_t)(bm + lrow) * K,
        Alo + (size_t)(bm + lrow) * K,
        Bhi + (size_t)(bn + lrow) * K,
        Blo + (size_t)(bn + lrow) * K
    };
    const uint32_t sd0 = lrow * 64 + SWZ(lrow, c0) * 16;
    const uint32_t sd1 = lrow * 64 + SWZ(lrow, c0 + 1) * 16;

    auto load_stage = [&](int s, int k0) {
        const uint32_t base = sbase + s * STAGE_BYTES;
#pragma unroll
        for (int p = 0; p < 4; p++) {
            const __nv_bfloat16* g = srcs[p] + k0;
            cp16(base + p * 8192 + sd0, g + c0 * 8);
            cp16(base + p * 8192 + sd1, g + (c0 + 1) * 8);
        }
        cp_commit();
    };

    float acc[4][4][4];
#pragma unroll
    for (int i = 0; i < 4; i++)
#pragma unroll
        for (int j = 0; j < 4; j++)
#pragma unroll
            for (int k = 0; k < 4; k++) acc[i][j][k] = 0.f;

    const int NIT = K >> 5;            // 32
    load_stage(0, 0);
    load_stage(1, 32);

    const int r16 = lane & 15;
    const int khalf = lane >> 4;

#pragma unroll 1
    for (int it = 0; it < NIT; it++) {
        // Stage `it` must be complete; allow the younger group to stay pending.
        if (it + 1 < NIT) cp_wait<1>(); else cp_wait<0>();
        __syncthreads();   // also guarantees everyone finished compute(it-1)

        // Prefetch distance 2: overwrite buffer (it-1)%3, now provably idle.
        if (it + 2 < NIT) {
            int s2 = it + 2;
            s2 -= (s2 / 3) * 3;
            load_stage(s2, (it + 2) * 32);
        }

        const int s = it - (it / 3) * 3;
        const uint32_t stbase = sbase + s * STAGE_BYTES;

        // Two K16 halves; odd warps take them in reverse order (anti-convoy).
        // Both halves live in the synced stage; accumulation order is free.
#pragma unroll
        for (int kx = 0; kx < 2; kx++) {
            const int half = kx ^ whalf;
            const int kc = half * 2 + khalf;    // 16B chunk index 0..3

            uint32_t bh[2][4], bl[2][4];
#pragma unroll
            for (int ng = 0; ng < 2; ng++) {
                const int row = wn + ng * 16 + r16;
                const uint32_t off = row * 64 + SWZ(row, kc) * 16;
                ldsm4(bh[ng], stbase + 16384 + off);   // B_hi plane
                ldsm4(bl[ng], stbase + 24576 + off);   // B_lo plane
            }
            // Per-mb: load A frags then immediately issue that mb's MMAs.
#pragma unroll
            for (int mb = 0; mb < 4; mb++) {
                uint32_t ah[4], al[4];
                const int row = wm + mb * 16 + r16;
                const uint32_t off = row * 64 + SWZ(row, kc) * 16;
                ldsm4(ah, stbase + off);               // A_hi plane
                ldsm4(al, stbase + 8192 + off);        // A_lo plane
#pragma unroll
                for (int nb = 0; nb < 4; nb++) {
                    const int ng = nb >> 1, j = nb & 1;
                    mma16816(acc[mb][nb], ah, bh[ng][j], bh[ng][2 + j]);
                    mma16816(acc[mb][nb], ah, bl[ng][j], bl[ng][2 + j]);
                    mma16816(acc[mb][nb], al, bh[ng][j], bh[ng][2 + j]);
                }
            }
        }
    }

    // ---- Epilogue: bias add, fp32 stores ----
    const int g  = lane >> 2;
    const int t2 = (lane & 3) * 2;
#pragma unroll
    for (int nb = 0; nb < 4; nb++) {
        const int col = bn + wn + nb * 8 + t2;
        const float bx = __ldg(bias + col), by = __ldg(bias + col + 1);
#pragma unroll
        for (int mb = 0; mb < 4; mb++) {
            const int row = bm + wm + mb * 16 + g;
            float2 v0 = make_float2(acc[mb][nb][0] + bx, acc[mb][nb][1] + by);
            float2 v1 = make_float2(acc[mb][nb][2] + bx, acc[mb][nb][3] + by);
            *(float2*)(C + (size_t)row * N + col)       = v0;
            *(float2*)(C + (size_t)(row + 8) * N + col) = v1;
        }
    }
}

// ---------------------------------------------------------------------------
// Banded attention: one warp per (b,t,h), 9-key window, warp-shfl reductions.
// Reads fp32 qkv [bt][ q | D+k | 2D+v ]; writes output directly as bf16 hi/lo
// planes (feeding GEMM2 without an fp32 round trip).
// ---------------------------------------------------------------------------
__global__ __launch_bounds__(256)
void focal_attn(const float* __restrict__ qkv,
                __nv_bfloat16* __restrict__ out_hi,
                __nv_bfloat16* __restrict__ out_lo)
{
    const int warp = threadIdx.x >> 5;
    const int lane = threadIdx.x & 31;
    const int gw = blockIdx.x * 8 + warp;     // 0 .. B*T*H-1
    const int h  = gw & (HEADS - 1);
    const int bt = gw >> 4;
    const int t  = bt & (TLEN - 1);
    const int b  = bt >> 11;

    const size_t row_stride = 3 * DMODEL;
    const int doff = h * HDIM + lane * 2;

    const float2 q = *(const float2*)(qkv + (size_t)bt * row_stride + doff);

    float s[9];
#pragma unroll
    for (int jj = 0; jj < 9; jj++) {
        const int j = t - RAD + jj;
        float val = -INFINITY;
        if (j >= 0 && j < TLEN) {
            const float2 kv = *(const float2*)(
                qkv + (size_t)(b * TLEN + j) * row_stride + DMODEL + doff);
            float p = q.x * kv.x + q.y * kv.y;
#pragma unroll
            for (int o = 16; o > 0; o >>= 1)
                p += __shfl_xor_sync(0xffffffffu, p, o);
            val = p * 0.125f;   // hd^-0.5
        }
        s[jj] = val;
    }

    float m = s[0];
#pragma unroll
    for (int jj = 1; jj < 9; jj++) m = fmaxf(m, s[jj]);

    float p[9], psum = 0.f;
#pragma unroll
    for (int jj = 0; jj < 9; jj++) {
        p[jj] = (s[jj] == -INFINITY) ? 0.f : expf(s[jj] - m);
        psum += p[jj];
    }
    const float inv = 1.f / psum;

    float2 acc = make_float2(0.f, 0.f);
#pragma unroll
    for (int jj = 0; jj < 9; jj++) {
        const int j = t - RAD + jj;
        if (j >= 0 && j < TLEN) {
            const float2 vv = *(const float2*)(
                qkv + (size_t)(b * TLEN + j) * row_stride + 2 * DMODEL + doff);
            acc.x = fmaf(p[jj], vv.x, acc.x);
            acc.y = fmaf(p[jj], vv.y, acc.y);
        }
    }
    acc.x *= inv;
    acc.y *= inv;

    const __nv_bfloat16 hx = __float2bfloat16(acc.x);
    const __nv_bfloat16 hy = __float2bfloat16(acc.y);
    __nv_bfloat162 hp; hp.x = hx; hp.y = hy;
    __nv_bfloat162 lp;
    lp.x = __float2bfloat16(acc.x - __bfloat162float(hx));
    lp.y = __float2bfloat16(acc.y - __bfloat162float(hy));
    *(__nv_bfloat162*)(out_hi + (size_t)bt * DMODEL + doff) = hp;
    *(__nv_bfloat162*)(out_lo + (size_t)bt * DMODEL + doff) = lp;
}

// ---------------------------------------------------------------------------
// Launch: split inputs -> QKV GEMM (tensor) -> attention -> proj GEMM (tensor)
// ---------------------------------------------------------------------------
extern "C" void kernel_launch(void* const* d_in, const int* in_sizes, int n_in,
                              void* d_out, int out_size)
{
    const float* x      = (const float*)d_in[0];
    const float* w_qkv  = (const float*)d_in[1];
    const float* b_qkv  = (const float*)d_in[2];
    const float* w_proj = (const float*)d_in[3];
    const float* b_proj = (const float*)d_in[4];
    float* out = (float*)d_out;

    float *qkv;
    __nv_bfloat16 *xhi, *xlo, *wqhi, *wqlo, *wphi, *wplo, *athi, *atlo;
    cudaGetSymbolAddress((void**)&qkv,  g_qkv);
    cudaGetSymbolAddress((void**)&xhi,  g_x_hi);
    cudaGetSymbolAddress((void**)&xlo,  g_x_lo);
    cudaGetSymbolAddress((void**)&wqhi, g_wq_hi);
    cudaGetSymbolAddress((void**)&wqlo, g_wq_lo);
    cudaGetSymbolAddress((void**)&wphi, g_wp_hi);
    cudaGetSymbolAddress((void**)&wplo, g_wp_lo);
    cudaGetSymbolAddress((void**)&athi, g_att_hi);
    cudaGetSymbolAddress((void**)&atlo, g_att_lo);

    cudaFuncSetAttribute(gemm_bf16x3,
                         cudaFuncAttributeMaxDynamicSharedMemorySize, GEMM_SMEM);

    // Split fp32 inputs into bf16 hi/lo planes
    {
        int n4 = MROWS * DMODEL / 4;
        split4<<<(n4 + 255) / 256, 256>>>((const float4*)x,
                                          (__nv_bfloat162*)xhi, (__nv_bfloat162*)xlo, n4);
        n4 = 3 * DMODEL * DMODEL / 4;
        split4<<<(n4 + 255) / 256, 256>>>((const float4*)w_qkv,
                                          (__nv_bfloat162*)wqhi, (__nv_bfloat162*)wqlo, n4);
        n4 = DMODEL * DMODEL / 4;
        split4<<<(n4 + 255) / 256, 256>>>((const float4*)w_proj,
                                          (__nv_bfloat162*)wphi, (__nv_bfloat162*)wplo, n4);
    }

    // GEMM1: qkv[8192,3072] = x @ w_qkv^T + b_qkv
    {
        dim3 grid(3 * DMODEL / 128, MROWS / 128);   // 24 x 64
        gemm_bf16x3<<<grid, 256, GEMM_SMEM>>>(xhi, xlo, wqhi, wqlo, b_qkv, qkv,
                                              MROWS, 3 * DMODEL, DMODEL);
    }

    // Attention: B*T*H warps
    {
        const int total_warps = BSZ * TLEN * HEADS;
        focal_attn<<<total_warps / 8, 256>>>(qkv, athi, atlo);
    }

    // GEMM2: out[8192,1024] = att @ w_proj^T + b_proj
    {
        dim3 grid(DMODEL / 128, MROWS / 128);       // 8 x 64
        gemm_bf16x3<<<grid, 256, GEMM_SMEM>>>(athi, atlo, wphi, wplo, b_proj, out,
                                              MROWS, DMODEL, DMODEL);
    }
}